// round 3
// baseline (speedup 1.0000x reference)
#include <cuda_runtime.h>
#include <cuda_bf16.h>
#include <math.h>

// Problem constants (Gemma attention, B=2,S=2048,HID=2048,H=8,KH=1,D=256)
#define BB   2
#define SS   2048
#define HID_ 2048
#define HH   8
#define DD   256

// ---------------------------------------------------------------------------
// Scratch (allocation-free: __device__ globals)
// ---------------------------------------------------------------------------
__device__ float g_q[(size_t)BB * SS * HH * DD];    // 33.5 MB
__device__ float g_k[(size_t)BB * SS * DD];         // 4 MB
__device__ float g_v[(size_t)BB * SS * DD];         // 4 MB
__device__ float g_vT[(size_t)BB * DD * SS];        // 4 MB
__device__ float g_ctx[(size_t)BB * SS * HH * DD];  // 33.5 MB

// ---------------------------------------------------------------------------
// Generic NT SGEMM:  C = alpha * (A @ B^T) + bias
//   A: (M,K) lda, B: (N,K) ldb, C: (M,N) ldc, all row-major.
//   Batched via blockIdx.z with (b,h) decomposition: z -> b=z/Hdim, h=z%Hdim.
//   All dims assumed multiples of tile sizes (true for every call here).
//   128x128 block tile, BK=8, 8x8 per thread, 256 threads.
// ---------------------------------------------------------------------------
__global__ __launch_bounds__(256, 2)
void sgemm_nt(const float* __restrict__ A, const float* __restrict__ B,
              const float* __restrict__ bias, float* __restrict__ C,
              int M, int N, int K, int lda, int ldb, int ldc,
              int Hdim,
              long long sAb, long long sAh,
              long long sBb, long long sBh,
              long long sCb, long long sCh,
              float alpha)
{
    const int BM = 128, BN = 128, BK = 8, TM = 8, TN = 8;

    int z  = blockIdx.z;
    int bz = z / Hdim;
    int hz = z - bz * Hdim;
    A += (long long)bz * sAb + (long long)hz * sAh;
    B += (long long)bz * sBb + (long long)hz * sBh;
    C += (long long)bz * sCb + (long long)hz * sCh;

    __shared__ float As[BK][BM];
    __shared__ float Bs[BK][BN];

    A += (long long)blockIdx.y * BM * lda;
    B += (long long)blockIdx.x * BN * ldb;
    C += (long long)blockIdx.y * BM * ldc + (long long)blockIdx.x * BN;

    const int tid  = threadIdx.x;
    const int rowL = tid >> 1;          // 0..127
    const int colL = (tid & 1) << 2;    // 0 or 4
    const int tr   = tid >> 4;          // 0..15
    const int tc   = tid & 15;          // 0..15

    float acc[TM][TN];
#pragma unroll
    for (int i = 0; i < TM; i++)
#pragma unroll
        for (int j = 0; j < TN; j++) acc[i][j] = 0.f;

    const float* Aptr = A + (long long)rowL * lda + colL;
    const float* Bptr = B + (long long)rowL * ldb + colL;

    for (int k0 = 0; k0 < K; k0 += BK) {
        float4 av = *(const float4*)(Aptr + k0);
        float4 bv = *(const float4*)(Bptr + k0);
        As[colL + 0][rowL] = av.x;
        As[colL + 1][rowL] = av.y;
        As[colL + 2][rowL] = av.z;
        As[colL + 3][rowL] = av.w;
        Bs[colL + 0][rowL] = bv.x;
        Bs[colL + 1][rowL] = bv.y;
        Bs[colL + 2][rowL] = bv.z;
        Bs[colL + 3][rowL] = bv.w;
        __syncthreads();

#pragma unroll
        for (int kk = 0; kk < BK; kk++) {
            float rm[TM], rn[TN];
#pragma unroll
            for (int i = 0; i < TM; i++) rm[i] = As[kk][tr * TM + i];
#pragma unroll
            for (int j = 0; j < TN; j++) rn[j] = Bs[kk][tc * TN + j];
#pragma unroll
            for (int i = 0; i < TM; i++)
#pragma unroll
                for (int j = 0; j < TN; j++) acc[i][j] += rm[i] * rn[j];
        }
        __syncthreads();
    }

    float bsr[TN];
#pragma unroll
    for (int j = 0; j < TN; j++)
        bsr[j] = bias ? bias[(long long)blockIdx.x * BN + tc * TN + j] : 0.f;

#pragma unroll
    for (int i = 0; i < TM; i++) {
        float4 o0, o1;
        o0.x = acc[i][0] * alpha + bsr[0];
        o0.y = acc[i][1] * alpha + bsr[1];
        o0.z = acc[i][2] * alpha + bsr[2];
        o0.w = acc[i][3] * alpha + bsr[3];
        o1.x = acc[i][4] * alpha + bsr[4];
        o1.y = acc[i][5] * alpha + bsr[5];
        o1.z = acc[i][6] * alpha + bsr[6];
        o1.w = acc[i][7] * alpha + bsr[7];
        float* cp = C + (long long)(tr * TM + i) * ldc + tc * TN;
        *(float4*)(cp)     = o0;
        *(float4*)(cp + 4) = o1;
    }
}

// ---------------------------------------------------------------------------
// RoPE (half-split convention): pairs (j, j+128) within each D=256 head dim.
// x layout: (B*S, Hx, 256). One thread per pair.
// ---------------------------------------------------------------------------
__global__ void rope_kernel(float* __restrict__ x, const int* __restrict__ pos,
                            int Hx, int total)
{
    int idx = blockIdx.x * blockDim.x + threadIdx.x;
    if (idx >= total) return;
    int j    = idx & 127;
    int rest = idx >> 7;
    int hh   = rest % Hx;
    int bs   = rest / Hx;                 // b*S + s
    float p  = (float)pos[bs];
    // inv_freq = 10000^(-j/128) = exp(-j * ln(10000)/128)
    float inv = __expf(-(float)j * (9.210340371976184f / 128.f));
    float f = p * inv;
    float sn, cs;
    sincosf(f, &sn, &cs);
    long long off = ((long long)bs * Hx + hh) * DD;
    float x1 = x[off + j];
    float x2 = x[off + 128 + j];
    x[off + j]       = cs * x1 - sn * x2;
    x[off + 128 + j] = sn * x1 + cs * x2;
}

// ---------------------------------------------------------------------------
// Transpose v (b,S,D) -> vT (b,D,S) for the NT AV GEMM.
// ---------------------------------------------------------------------------
__global__ void transpose_SD(const float* __restrict__ v, float* __restrict__ vT)
{
    __shared__ float t[32][33];
    int b  = blockIdx.z;
    int s0 = blockIdx.x * 32;
    int d0 = blockIdx.y * 32;
    int tx = threadIdx.x, ty = threadIdx.y;   // (32, 8)
    const float* src = v  + (long long)b * SS * DD;
    float*       dst = vT + (long long)b * DD * SS;
#pragma unroll
    for (int i = 0; i < 32; i += 8)
        t[ty + i][tx] = src[(long long)(s0 + ty + i) * DD + d0 + tx];
    __syncthreads();
#pragma unroll
    for (int i = 0; i < 32; i += 8)
        dst[(long long)(d0 + ty + i) * SS + s0 + tx] = t[tx][ty + i];
}

// ---------------------------------------------------------------------------
// Row softmax over attn (B,H,S,S), in place, with additive mask[b, col].
// One block of 256 threads per row (S=2048 -> 8 elems/thread).
// ---------------------------------------------------------------------------
__global__ __launch_bounds__(256)
void softmax_rows(float* __restrict__ attn, const float* __restrict__ mask)
{
    const int HSrows = HH * SS;               // rows per batch
    long long r = blockIdx.x;
    int b = (int)(r / HSrows);
    float* row = attn + r * (long long)SS;
    const float* mrow = mask + (long long)b * SS;

    int tid  = threadIdx.x;
    int w    = tid >> 5;
    int lane = tid & 31;
    __shared__ float red[8];

    float v[8];
    float mx = -1e30f;
#pragma unroll
    for (int i = 0; i < 8; i++) {
        int c = tid + i * 256;
        float x = row[c] + mrow[c];
        v[i] = x;
        mx = fmaxf(mx, x);
    }
#pragma unroll
    for (int o = 16; o; o >>= 1) mx = fmaxf(mx, __shfl_xor_sync(0xffffffffu, mx, o));
    if (lane == 0) red[w] = mx;
    __syncthreads();
#pragma unroll
    for (int i = 0; i < 8; i++) mx = fmaxf(mx, red[i]);

    float s = 0.f;
#pragma unroll
    for (int i = 0; i < 8; i++) {
        v[i] = expf(v[i] - mx);
        s += v[i];
    }
#pragma unroll
    for (int o = 16; o; o >>= 1) s += __shfl_xor_sync(0xffffffffu, s, o);
    __syncthreads();                           // protect red reuse
    if (lane == 0) red[w] = s;
    __syncthreads();
    s = 0.f;
#pragma unroll
    for (int i = 0; i < 8; i++) s += red[i];
    float inv = 1.f / s;
#pragma unroll
    for (int i = 0; i < 8; i++) row[tid + i * 256] = v[i] * inv;
}

// ---------------------------------------------------------------------------
// Launch
// ---------------------------------------------------------------------------
extern "C" void kernel_launch(void* const* d_in, const int* in_sizes, int n_in,
                              void* d_out, int out_size)
{
    (void)in_sizes; (void)n_in; (void)out_size;

    const float* hidden = (const float*)d_in[0];
    const float* mask   = (const float*)d_in[1];
    const int*   pos    = (const int*)  d_in[2];
    const float* Wq     = (const float*)d_in[3];
    const float* bq     = (const float*)d_in[4];
    const float* Wk     = (const float*)d_in[5];
    const float* bk     = (const float*)d_in[6];
    const float* Wv     = (const float*)d_in[7];
    const float* bv     = (const float*)d_in[8];
    const float* Wo     = (const float*)d_in[9];
    const float* bo     = (const float*)d_in[10];

    float* out  = (float*)d_out;                            // (B,S,HID)
    float* attn = out + (size_t)BB * SS * HID_;             // (B,H,S,S)

    float *q, *k, *v, *vT, *ctx;
    cudaGetSymbolAddress((void**)&q,   g_q);
    cudaGetSymbolAddress((void**)&k,   g_k);
    cudaGetSymbolAddress((void**)&v,   g_v);
    cudaGetSymbolAddress((void**)&vT,  g_vT);
    cudaGetSymbolAddress((void**)&ctx, g_ctx);

    const int M  = BB * SS;          // 4096 flattened tokens
    dim3 blk(256);

    // 1) Q = hidden @ Wq^T + bq      (4096 x 2048 x 2048)
    sgemm_nt<<<dim3(HID_ / 128, M / 128, 1), blk>>>(
        hidden, Wq, bq, q, M, HH * DD, HID_, HID_, HID_, HH * DD,
        1, 0, 0, 0, 0, 0, 0, 1.0f);

    // 2) K = hidden @ Wk^T + bk      (4096 x 256 x 2048)
    sgemm_nt<<<dim3(DD / 128, M / 128, 1), blk>>>(
        hidden, Wk, bk, k, M, DD, HID_, HID_, HID_, DD,
        1, 0, 0, 0, 0, 0, 0, 1.0f);

    // 3) V = hidden @ Wv^T + bv      (4096 x 256 x 2048)
    sgemm_nt<<<dim3(DD / 128, M / 128, 1), blk>>>(
        hidden, Wv, bv, v, M, DD, HID_, HID_, HID_, DD,
        1, 0, 0, 0, 0, 0, 0, 1.0f);

    // 4) RoPE on q and k
    {
        int totq = BB * SS * HH * (DD / 2);   // 4,194,304
        rope_kernel<<<(totq + 255) / 256, blk>>>(q, pos, HH, totq);
        int totk = BB * SS * 1 * (DD / 2);    // 524,288
        rope_kernel<<<(totk + 255) / 256, blk>>>(k, pos, 1, totk);
    }

    // 5) vT (b,D,S)
    transpose_SD<<<dim3(SS / 32, DD / 32, BB), dim3(32, 8)>>>(v, vT);

    // 6) scores = (q_bh @ k_b^T) / 16  -> attn region   (per (b,h): 2048x2048x256)
    sgemm_nt<<<dim3(SS / 128, SS / 128, BB * HH), blk>>>(
        q, k, nullptr, attn, SS, SS, DD,
        HH * DD, DD, SS,
        HH,
        (long long)SS * HH * DD, (long long)DD,      // A: q (b,s,h,d)
        (long long)SS * DD, 0,                       // B: k (b,s,d)
        (long long)HH * SS * SS, (long long)SS * SS, // C: attn (b,h,n,m)
        0.0625f);

    // 7) softmax rows in place (+mask)
    softmax_rows<<<BB * HH * SS, blk>>>(attn, mask);

    // 8) ctx = attn @ v   (per (b,h): 2048x256x2048, NT against vT)
    sgemm_nt<<<dim3(DD / 128, SS / 128, BB * HH), blk>>>(
        attn, vT, nullptr, ctx, SS, DD, SS,
        SS, SS, HH * DD,
        HH,
        (long long)HH * SS * SS, (long long)SS * SS, // A: attn
        (long long)DD * SS, 0,                       // B: vT (b,d,s)
        (long long)SS * HH * DD, (long long)DD,      // C: ctx (b,s,h,d)
        1.0f);

    // 9) out = ctx @ Wo^T + bo       (4096 x 2048 x 2048)
    sgemm_nt<<<dim3(HID_ / 128, M / 128, 1), blk>>>(
        ctx, Wo, bo, out, M, HID_, HH * DD, HH * DD, HH * DD, HID_,
        1, 0, 0, 0, 0, 0, 0, 1.0f);
}

// round 5
// speedup vs baseline: 2.1633x; 2.1633x over previous
#include <cuda_runtime.h>
#include <cuda_bf16.h>
#include <math.h>
#include <stdint.h>

// Problem constants (Gemma attention, B=2,S=2048,HID=2048,H=8,KH=1,D=256)
#define BB   2
#define SS   2048
#define HID_ 2048
#define HH   8
#define DD   256

typedef __nv_bfloat16 bf16;
typedef __nv_bfloat162 bf162;

// ---------------------------------------------------------------------------
// Scratch (__device__ globals — allocation-free)
// ---------------------------------------------------------------------------
__device__ float g_q[(size_t)BB * SS * HH * DD];
__device__ float g_k[(size_t)BB * SS * DD];
__device__ float g_v[(size_t)BB * SS * DD];

__device__ bf16 g_hidH[(size_t)BB * SS * HID_], g_hidL[(size_t)BB * SS * HID_];
__device__ bf16 g_WqH[(size_t)HH * DD * HID_], g_WqL[(size_t)HH * DD * HID_];
__device__ bf16 g_WkH[(size_t)DD * HID_],      g_WkL[(size_t)DD * HID_];
__device__ bf16 g_WvH[(size_t)DD * HID_],      g_WvL[(size_t)DD * HID_];
__device__ bf16 g_WoH[(size_t)HID_ * HH * DD], g_WoL[(size_t)HID_ * HH * DD];
__device__ bf16 g_qH[(size_t)BB * SS * HH * DD], g_qL[(size_t)BB * SS * HH * DD];
__device__ bf16 g_kH[(size_t)BB * SS * DD],      g_kL[(size_t)BB * SS * DD];
__device__ bf16 g_vTH[(size_t)BB * DD * SS],     g_vTL[(size_t)BB * DD * SS];
__device__ bf16 g_attnH[(size_t)BB * HH * SS * SS];   // 134 MB
__device__ bf16 g_attnL[(size_t)BB * HH * SS * SS];   // 134 MB
__device__ bf16 g_ctxH[(size_t)BB * SS * HH * DD],  g_ctxL[(size_t)BB * SS * HH * DD];

// ---------------------------------------------------------------------------
// PTX helpers (sm_80-era: cp.async / ldmatrix / mma.sync — valid on sm_103)
// ---------------------------------------------------------------------------
__device__ __forceinline__ uint32_t smem_u32(const void* p) {
    uint32_t a;
    asm("{ .reg .u64 t; cvta.to.shared.u64 t, %1; cvt.u32.u64 %0, t; }"
        : "=r"(a) : "l"(p));
    return a;
}

__device__ __forceinline__ void cp16(uint32_t dst, const void* src) {
    asm volatile("cp.async.cg.shared.global [%0], [%1], 16;"
                 :: "r"(dst), "l"(src) : "memory");
}
#define CP_COMMIT() asm volatile("cp.async.commit_group;" ::: "memory")
#define CP_WAIT(n)  asm volatile("cp.async.wait_group %0;" :: "n"(n) : "memory")

__device__ __forceinline__ void ldm_x4(uint32_t* r, uint32_t addr) {
    asm volatile("ldmatrix.sync.aligned.m8n8.x4.shared.b16 {%0,%1,%2,%3}, [%4];"
                 : "=r"(r[0]), "=r"(r[1]), "=r"(r[2]), "=r"(r[3]) : "r"(addr));
}

__device__ __forceinline__ void mma_bf16(float* c, const uint32_t* a,
                                         uint32_t b0, uint32_t b1) {
    asm volatile(
        "mma.sync.aligned.m16n8k16.row.col.f32.bf16.bf16.f32 "
        "{%0,%1,%2,%3}, {%4,%5,%6,%7}, {%8,%9}, {%0,%1,%2,%3};"
        : "+f"(c[0]), "+f"(c[1]), "+f"(c[2]), "+f"(c[3])
        : "r"(a[0]), "r"(a[1]), "r"(a[2]), "r"(a[3]), "r"(b0), "r"(b1));
}

__device__ __forceinline__ void split1(float v, bf16& h, bf16& l) {
    h = __float2bfloat16(v);
    l = __float2bfloat16(v - __bfloat162float(h));
}

// ===========================================================================
// Split-bf16 NT GEMM on HMMA:  C = alpha*(Ah·Bh^T + Al·Bh^T + Ah·Bl^T) + bias
//   A hi/lo: (M,K) bf16 lda; B hi/lo: (N,K) bf16 ldb; C fp32 (M,N) ldc.
//   Optional split-bf16 C output (Ch/Cl). Tile 128x128x32, 256 thr, 3-stage
//   cp.async pipeline. All dims multiples of (128,128,32).
// ===========================================================================
#define ROWB    80                 // 32 bf16 (64B) + 16B pad
#define TILE_B  (128 * ROWB)       // 10240 B
#define STAGE_B (4 * TILE_B)       // Ah,Al,Bh,Bl
#define NSTAGE  3
#define HGEMM_SMEM (NSTAGE * STAGE_B)   // 122880 B

__global__ __launch_bounds__(256, 1)
void hgemm_nt(const bf16* __restrict__ Ah, const bf16* __restrict__ Al,
              const bf16* __restrict__ Bh, const bf16* __restrict__ Bl,
              const float* __restrict__ bias,
              float* __restrict__ C, bf16* __restrict__ Ch, bf16* __restrict__ Cl,
              int K, int lda, int ldb, int ldc, int Hdim,
              long long sAb, long long sAh_,
              long long sBb, long long sBh_,
              long long sCb, long long sCh_,
              float alpha)
{
    extern __shared__ __align__(128) char smem[];
    const uint32_t sb = smem_u32(smem);

    const int tid  = threadIdx.x;
    const int wid  = tid >> 5;
    const int lane = tid & 31;
    const int wm   = wid >> 2;          // 0..1  (64-row band)
    const int wn   = wid & 3;           // 0..3  (32-col band)

    // batch decomposition
    {
        int z  = blockIdx.z;
        int bz = z / Hdim;
        int hz = z - bz * Hdim;
        long long oA = (long long)bz * sAb + (long long)hz * sAh_
                     + (long long)blockIdx.y * 128 * lda;
        long long oB = (long long)bz * sBb + (long long)hz * sBh_
                     + (long long)blockIdx.x * 128 * ldb;
        long long oC = (long long)bz * sCb + (long long)hz * sCh_
                     + (long long)blockIdx.y * 128 * ldc + (long long)blockIdx.x * 128;
        Ah += oA; Al += oA; Bh += oB; Bl += oB;
        if (C)  C  += oC;
        if (Ch) { Ch += oC; Cl += oC; }
    }

    const int nc = K >> 5;

    // per-thread cp.async source/dest mapping: row = tid/2, 2x16B chunks
    const int lrow = tid >> 1;
    const int lco  = (tid & 1) * 16;    // elem offset within 32-elem row
    const bf16* gAh = Ah + (long long)lrow * lda + lco;
    const bf16* gAl = Al + (long long)lrow * lda + lco;
    const bf16* gBh = Bh + (long long)lrow * ldb + lco;
    const bf16* gBl = Bl + (long long)lrow * ldb + lco;
    const uint32_t dbase = sb + lrow * ROWB + (tid & 1) * 32;

    auto issue = [&](int stage, int c) {
        if (c < nc) {
            const int k0 = c << 5;
            uint32_t d = dbase + stage * STAGE_B;
            cp16(d,                  gAh + k0); cp16(d + 16,              gAh + k0 + 8);
            cp16(d + TILE_B,         gAl + k0); cp16(d + TILE_B + 16,     gAl + k0 + 8);
            cp16(d + 2 * TILE_B,     gBh + k0); cp16(d + 2 * TILE_B + 16, gBh + k0 + 8);
            cp16(d + 3 * TILE_B,     gBl + k0); cp16(d + 3 * TILE_B + 16, gBl + k0 + 8);
        }
        CP_COMMIT();
    };

    float acc[4][4][4];
#pragma unroll
    for (int i = 0; i < 4; i++)
#pragma unroll
        for (int j = 0; j < 4; j++)
#pragma unroll
            for (int r = 0; r < 4; r++) acc[i][j][r] = 0.f;

    issue(0, 0);
    issue(1, 1);

    // ldmatrix lane address component (within a tile)
    const uint32_t loff =
        (uint32_t)((lane & 7) + ((lane >> 3) & 1) * 8) * ROWB + ((lane >> 4) << 4);

    for (int c = 0; c < nc; c++) {
        CP_WAIT(1);
        __syncthreads();
        issue((c + 2) % NSTAGE, c + 2);

        const uint32_t st = sb + (c % NSTAGE) * STAGE_B;
        const uint32_t aBase = st + (wm * 64) * ROWB + loff;
        const uint32_t bBase = st + 2 * TILE_B + (wn * 32) * ROWB + loff;

#pragma unroll
        for (int k16 = 0; k16 < 2; k16++) {
            const uint32_t kb = k16 * 32;
            uint32_t aH[4][4], aL[4][4], bH[2][4], bL[2][4];
#pragma unroll
            for (int mt = 0; mt < 4; mt++) {
                ldm_x4(aH[mt], aBase + mt * (16 * ROWB) + kb);
                ldm_x4(aL[mt], aBase + TILE_B + mt * (16 * ROWB) + kb);
            }
#pragma unroll
            for (int nt = 0; nt < 2; nt++) {
                ldm_x4(bH[nt], bBase + nt * (16 * ROWB) + kb);
                ldm_x4(bL[nt], bBase + TILE_B + nt * (16 * ROWB) + kb);
            }
#pragma unroll
            for (int mt = 0; mt < 4; mt++)
#pragma unroll
                for (int j = 0; j < 4; j++) {
                    const int nt = j >> 1, h = j & 1;
                    mma_bf16(acc[mt][j], aH[mt], bH[nt][h], bH[nt][2 + h]);
                    mma_bf16(acc[mt][j], aL[mt], bH[nt][h], bH[nt][2 + h]);
                    mma_bf16(acc[mt][j], aH[mt], bL[nt][h], bL[nt][2 + h]);
                }
        }
    }

    // ---- epilogue ----
    const int colblk = blockIdx.x << 7;
#pragma unroll
    for (int mt = 0; mt < 4; mt++) {
        const int row0 = wm * 64 + mt * 16 + (lane >> 2);
#pragma unroll
        for (int hrow = 0; hrow < 2; hrow++) {
            const int row = row0 + hrow * 8;
#pragma unroll
            for (int j = 0; j < 4; j++) {
                const int col = wn * 32 + j * 8 + (lane & 3) * 2;
                float b0 = 0.f, b1 = 0.f;
                if (bias) { b0 = bias[colblk + col]; b1 = bias[colblk + col + 1]; }
                float v0 = acc[mt][j][hrow * 2 + 0] * alpha + b0;
                float v1 = acc[mt][j][hrow * 2 + 1] * alpha + b1;
                const long long ci = (long long)row * ldc + col;
                if (C) *(float2*)(C + ci) = make_float2(v0, v1);
                if (Ch) {
                    bf16 h0, l0, h1, l1;
                    split1(v0, h0, l0);
                    split1(v1, h1, l1);
                    *(bf162*)(Ch + ci) = __halves2bfloat162(h0, h1);
                    *(bf162*)(Cl + ci) = __halves2bfloat162(l0, l1);
                }
            }
        }
    }
}

// ---------------------------------------------------------------------------
// Elementwise fp32 -> (hi,lo) bf16 split
// ---------------------------------------------------------------------------
__global__ void split_arr(const float* __restrict__ s, bf16* __restrict__ h,
                          bf16* __restrict__ l, long long n)
{
    long long i = ((long long)blockIdx.x * blockDim.x + threadIdx.x) * 4;
    if (i >= n) return;
    float4 v = *(const float4*)(s + i);
    bf16 h0, l0, h1, l1, h2, l2, h3, l3;
    split1(v.x, h0, l0); split1(v.y, h1, l1);
    split1(v.z, h2, l2); split1(v.w, h3, l3);
    *(bf162*)(h + i)     = __halves2bfloat162(h0, h1);
    *(bf162*)(h + i + 2) = __halves2bfloat162(h2, h3);
    *(bf162*)(l + i)     = __halves2bfloat162(l0, l1);
    *(bf162*)(l + i + 2) = __halves2bfloat162(l2, l3);
}

// ---------------------------------------------------------------------------
// RoPE + split: reads fp32 x (B*S, Hx, 256), writes rotated hi/lo bf16
// ---------------------------------------------------------------------------
__global__ void rope_split(const float* __restrict__ x, const int* __restrict__ pos,
                           bf16* __restrict__ xh, bf16* __restrict__ xl,
                           int Hx, int total)
{
    int idx = blockIdx.x * blockDim.x + threadIdx.x;
    if (idx >= total) return;
    int j    = idx & 127;
    int rest = idx >> 7;
    int hh   = rest % Hx;
    int bs   = rest / Hx;
    float p  = (float)pos[bs];
    float inv = __expf(-(float)j * (9.210340371976184f / 128.f));
    float f = p * inv;
    float sn, cs;
    sincosf(f, &sn, &cs);
    long long off = ((long long)bs * Hx + hh) * DD;
    float x1 = x[off + j];
    float x2 = x[off + 128 + j];
    float y1 = cs * x1 - sn * x2;
    float y2 = sn * x1 + cs * x2;
    bf16 h, l;
    split1(y1, h, l); xh[off + j] = h;        xl[off + j] = l;
    split1(y2, h, l); xh[off + 128 + j] = h;  xl[off + 128 + j] = l;
}

// ---------------------------------------------------------------------------
// Transpose v (b,S,D) fp32 -> vT (b,D,S) split bf16
// ---------------------------------------------------------------------------
__global__ void transpose_split(const float* __restrict__ v,
                                bf16* __restrict__ vTh, bf16* __restrict__ vTl)
{
    __shared__ float t[32][33];
    int b  = blockIdx.z;
    int s0 = blockIdx.x * 32;
    int d0 = blockIdx.y * 32;
    int tx = threadIdx.x, ty = threadIdx.y;
    const float* src = v + (long long)b * SS * DD;
#pragma unroll
    for (int i = 0; i < 32; i += 8)
        t[ty + i][tx] = src[(long long)(s0 + ty + i) * DD + d0 + tx];
    __syncthreads();
    long long obase = (long long)b * DD * SS;
#pragma unroll
    for (int i = 0; i < 32; i += 8) {
        long long oi = obase + (long long)(d0 + ty + i) * SS + s0 + tx;
        bf16 h, l;
        split1(t[tx][ty + i], h, l);
        vTh[oi] = h;
        vTl[oi] = l;
    }
}

// ---------------------------------------------------------------------------
// Row softmax over attn (B,H,S,S) in place (+mask), also emits split bf16
// ---------------------------------------------------------------------------
__global__ __launch_bounds__(256)
void softmax_split(float* __restrict__ attn, const float* __restrict__ mask,
                   bf16* __restrict__ ah, bf16* __restrict__ al)
{
    const int HSrows = HH * SS;
    long long r = blockIdx.x;
    int b = (int)(r / HSrows);
    float* row = attn + r * (long long)SS;
    const float* mrow = mask + (long long)b * SS;

    int tid  = threadIdx.x;
    int w    = tid >> 5;
    int lane = tid & 31;
    __shared__ float red[8];

    float v[8];
    float mx = -1e30f;
#pragma unroll
    for (int i = 0; i < 8; i++) {
        int c = tid + i * 256;
        float x = row[c] + mrow[c];
        v[i] = x;
        mx = fmaxf(mx, x);
    }
#pragma unroll
    for (int o = 16; o; o >>= 1) mx = fmaxf(mx, __shfl_xor_sync(0xffffffffu, mx, o));
    if (lane == 0) red[w] = mx;
    __syncthreads();
#pragma unroll
    for (int i = 0; i < 8; i++) mx = fmaxf(mx, red[i]);

    float s = 0.f;
#pragma unroll
    for (int i = 0; i < 8; i++) {
        v[i] = expf(v[i] - mx);
        s += v[i];
    }
#pragma unroll
    for (int o = 16; o; o >>= 1) s += __shfl_xor_sync(0xffffffffu, s, o);
    __syncthreads();
    if (lane == 0) red[w] = s;
    __syncthreads();
    s = 0.f;
#pragma unroll
    for (int i = 0; i < 8; i++) s += red[i];
    float inv = 1.f / s;

    long long rb = r * (long long)SS;
#pragma unroll
    for (int i = 0; i < 8; i++) {
        int c = tid + i * 256;
        float p = v[i] * inv;
        row[c] = p;
        bf16 h, l;
        split1(p, h, l);
        ah[rb + c] = h;
        al[rb + c] = l;
    }
}

// ---------------------------------------------------------------------------
// Launch
// ---------------------------------------------------------------------------
extern "C" void kernel_launch(void* const* d_in, const int* in_sizes, int n_in,
                              void* d_out, int out_size)
{
    (void)in_sizes; (void)n_in; (void)out_size;

    const float* hidden = (const float*)d_in[0];
    const float* mask   = (const float*)d_in[1];
    const int*   pos    = (const int*)  d_in[2];
    const float* Wq     = (const float*)d_in[3];
    const float* bq     = (const float*)d_in[4];
    const float* Wk     = (const float*)d_in[5];
    const float* bk     = (const float*)d_in[6];
    const float* Wv     = (const float*)d_in[7];
    const float* bv     = (const float*)d_in[8];
    const float* Wo     = (const float*)d_in[9];
    const float* bo     = (const float*)d_in[10];

    float* out  = (float*)d_out;                      // (B,S,HID)
    float* attn = out + (size_t)BB * SS * HID_;       // (B,H,S,S)

    float *q, *k, *v;
    bf16 *hidH, *hidL, *WqH, *WqL, *WkH, *WkL, *WvH, *WvL, *WoH, *WoL;
    bf16 *qH, *qL, *kH, *kL, *vTH, *vTL, *attnH, *attnL, *ctxH, *ctxL;
    cudaGetSymbolAddress((void**)&q, g_q);
    cudaGetSymbolAddress((void**)&k, g_k);
    cudaGetSymbolAddress((void**)&v, g_v);
    cudaGetSymbolAddress((void**)&hidH, g_hidH);  cudaGetSymbolAddress((void**)&hidL, g_hidL);
    cudaGetSymbolAddress((void**)&WqH, g_WqH);    cudaGetSymbolAddress((void**)&WqL, g_WqL);
    cudaGetSymbolAddress((void**)&WkH, g_WkH);    cudaGetSymbolAddress((void**)&WkL, g_WkL);
    cudaGetSymbolAddress((void**)&WvH, g_WvH);    cudaGetSymbolAddress((void**)&WvL, g_WvL);
    cudaGetSymbolAddress((void**)&WoH, g_WoH);    cudaGetSymbolAddress((void**)&WoL, g_WoL);
    cudaGetSymbolAddress((void**)&qH, g_qH);      cudaGetSymbolAddress((void**)&qL, g_qL);
    cudaGetSymbolAddress((void**)&kH, g_kH);      cudaGetSymbolAddress((void**)&kL, g_kL);
    cudaGetSymbolAddress((void**)&vTH, g_vTH);    cudaGetSymbolAddress((void**)&vTL, g_vTL);
    cudaGetSymbolAddress((void**)&attnH, g_attnH); cudaGetSymbolAddress((void**)&attnL, g_attnL);
    cudaGetSymbolAddress((void**)&ctxH, g_ctxH);  cudaGetSymbolAddress((void**)&ctxL, g_ctxL);

    cudaFuncSetAttribute(hgemm_nt, cudaFuncAttributeMaxDynamicSharedMemorySize,
                         HGEMM_SMEM);

    const int M = BB * SS;   // 4096
    dim3 blk(256);

    // 0) split inputs
    {
        long long n;
        n = (long long)BB * SS * HID_;
        split_arr<<<(unsigned)((n / 4 + 255) / 256), blk>>>(hidden, hidH, hidL, n);
        n = (long long)HH * DD * HID_;
        split_arr<<<(unsigned)((n / 4 + 255) / 256), blk>>>(Wq, WqH, WqL, n);
        n = (long long)DD * HID_;
        split_arr<<<(unsigned)((n / 4 + 255) / 256), blk>>>(Wk, WkH, WkL, n);
        split_arr<<<(unsigned)((n / 4 + 255) / 256), blk>>>(Wv, WvH, WvL, n);
        n = (long long)HID_ * HH * DD;
        split_arr<<<(unsigned)((n / 4 + 255) / 256), blk>>>(Wo, WoH, WoL, n);
    }

    // 1) Q/K/V projections (fp32 outputs)
    hgemm_nt<<<dim3((HH * DD) / 128, M / 128, 1), blk, HGEMM_SMEM>>>(
        hidH, hidL, WqH, WqL, bq, q, nullptr, nullptr,
        HID_, HID_, HID_, HH * DD, 1, 0, 0, 0, 0, 0, 0, 1.0f);
    hgemm_nt<<<dim3(DD / 128, M / 128, 1), blk, HGEMM_SMEM>>>(
        hidH, hidL, WkH, WkL, bk, k, nullptr, nullptr,
        HID_, HID_, HID_, DD, 1, 0, 0, 0, 0, 0, 0, 1.0f);
    hgemm_nt<<<dim3(DD / 128, M / 128, 1), blk, HGEMM_SMEM>>>(
        hidH, hidL, WvH, WvL, bv, v, nullptr, nullptr,
        HID_, HID_, HID_, DD, 1, 0, 0, 0, 0, 0, 0, 1.0f);

    // 2) RoPE + split q, k
    {
        int totq = BB * SS * HH * (DD / 2);
        rope_split<<<(totq + 255) / 256, blk>>>(q, pos, qH, qL, HH, totq);
        int totk = BB * SS * (DD / 2);
        rope_split<<<(totk + 255) / 256, blk>>>(k, pos, kH, kL, 1, totk);
    }

    // 3) vT split (b,D,S)
    transpose_split<<<dim3(SS / 32, DD / 32, BB), dim3(32, 8)>>>(v, vTH, vTL);

    // 4) scores = (q @ k^T)/16 -> attn fp32 region
    hgemm_nt<<<dim3(SS / 128, SS / 128, BB * HH), blk, HGEMM_SMEM>>>(
        qH, qL, kH, kL, nullptr, attn, nullptr, nullptr,
        DD, HH * DD, DD, SS, HH,
        (long long)SS * HH * DD, (long long)DD,
        (long long)SS * DD, 0,
        (long long)HH * SS * SS, (long long)SS * SS,
        0.0625f);

    // 5) softmax in place + split output
    softmax_split<<<BB * HH * SS, blk>>>(attn, mask, attnH, attnL);

    // 6) ctx = attn @ v  -> split bf16 directly
    hgemm_nt<<<dim3(DD / 128, SS / 128, BB * HH), blk, HGEMM_SMEM>>>(
        attnH, attnL, vTH, vTL, nullptr, nullptr, ctxH, ctxL,
        SS, SS, SS, HH * DD, HH,
        (long long)HH * SS * SS, (long long)SS * SS,
        (long long)DD * SS, 0,
        (long long)SS * HH * DD, (long long)DD,
        1.0f);

    // 7) out = ctx @ Wo^T + bo
    hgemm_nt<<<dim3(HID_ / 128, M / 128, 1), blk, HGEMM_SMEM>>>(
        ctxH, ctxL, WoH, WoL, bo, out, nullptr, nullptr,
        HH * DD, HH * DD, HH * DD, HID_, 1, 0, 0, 0, 0, 0, 0, 1.0f);
}

// round 6
// speedup vs baseline: 2.3859x; 1.1029x over previous
#include <cuda_runtime.h>
#include <cuda_bf16.h>
#include <math.h>
#include <stdint.h>

// Problem constants (Gemma attention, B=2,S=2048,HID=2048,H=8,KH=1,D=256)
#define BB   2
#define SS   2048
#define HID_ 2048
#define HH   8
#define DD   256
#define NQKV 2560   // packed Q(2048) + K(256) + V(256)

typedef __nv_bfloat16 bf16;
typedef __nv_bfloat162 bf162;

// ---------------------------------------------------------------------------
// Scratch (__device__ globals — allocation-free)
// ---------------------------------------------------------------------------
__device__ float g_qkv[(size_t)BB * SS * NQKV];       // 41.9 MB fp32 qkv proj
__device__ float g_bqkv[NQKV];

__device__ bf16 g_hidH[(size_t)BB * SS * HID_], g_hidL[(size_t)BB * SS * HID_];
__device__ bf16 g_WqkvH[(size_t)NQKV * HID_],  g_WqkvL[(size_t)NQKV * HID_];
__device__ bf16 g_WoH[(size_t)HID_ * HH * DD], g_WoL[(size_t)HID_ * HH * DD];
__device__ bf16 g_qH[(size_t)BB * SS * HH * DD], g_qL[(size_t)BB * SS * HH * DD];
__device__ bf16 g_kH[(size_t)BB * SS * DD],      g_kL[(size_t)BB * SS * DD];
__device__ bf16 g_vTH[(size_t)BB * DD * SS],     g_vTL[(size_t)BB * DD * SS];
__device__ bf16 g_attnH[(size_t)BB * HH * SS * SS];   // 134 MB
__device__ bf16 g_attnL[(size_t)BB * HH * SS * SS];   // 134 MB
__device__ bf16 g_ctxH[(size_t)BB * SS * HH * DD],  g_ctxL[(size_t)BB * SS * HH * DD];

// ---------------------------------------------------------------------------
// PTX helpers (sm_80-era: cp.async / ldmatrix / mma.sync — valid on sm_103)
// ---------------------------------------------------------------------------
__device__ __forceinline__ uint32_t smem_u32(const void* p) {
    uint32_t a;
    asm("{ .reg .u64 t; cvta.to.shared.u64 t, %1; cvt.u32.u64 %0, t; }"
        : "=r"(a) : "l"(p));
    return a;
}

__device__ __forceinline__ void cp16(uint32_t dst, const void* src) {
    asm volatile("cp.async.cg.shared.global [%0], [%1], 16;"
                 :: "r"(dst), "l"(src) : "memory");
}
#define CP_COMMIT() asm volatile("cp.async.commit_group;" ::: "memory")
#define CP_WAIT(n)  asm volatile("cp.async.wait_group %0;" :: "n"(n) : "memory")

__device__ __forceinline__ void ldm_x4(uint32_t* r, uint32_t addr) {
    asm volatile("ldmatrix.sync.aligned.m8n8.x4.shared.b16 {%0,%1,%2,%3}, [%4];"
                 : "=r"(r[0]), "=r"(r[1]), "=r"(r[2]), "=r"(r[3]) : "r"(addr));
}

__device__ __forceinline__ void mma_bf16(float* c, const uint32_t* a,
                                         uint32_t b0, uint32_t b1) {
    asm volatile(
        "mma.sync.aligned.m16n8k16.row.col.f32.bf16.bf16.f32 "
        "{%0,%1,%2,%3}, {%4,%5,%6,%7}, {%8,%9}, {%0,%1,%2,%3};"
        : "+f"(c[0]), "+f"(c[1]), "+f"(c[2]), "+f"(c[3])
        : "r"(a[0]), "r"(a[1]), "r"(a[2]), "r"(a[3]), "r"(b0), "r"(b1));
}

__device__ __forceinline__ void split1(float v, bf16& h, bf16& l) {
    h = __float2bfloat16(v);
    l = __float2bfloat16(v - __bfloat162float(h));
}

// ===========================================================================
// Split-bf16 NT GEMM on HMMA:  C = alpha*(Ah·Bh^T + Al·Bh^T + Ah·Bl^T) + bias
//   Tile 256x128x32, 512 threads (16 warps, warp tile 64x32), 3-stage
//   cp.async pipeline. All dims multiples of (256,128,32).
// ===========================================================================
#define ROWB    80                  // 32 bf16 (64B) + 16B pad
#define A_T_B   (256 * ROWB)        // 20480
#define B_T_B   (128 * ROWB)        // 10240
#define OFF_AL  A_T_B               // 20480
#define OFF_BH  (2 * A_T_B)         // 40960
#define OFF_BL  (2 * A_T_B + B_T_B) // 51200
#define STAGE_B (2 * A_T_B + 2 * B_T_B)   // 61440
#define NSTAGE  3
#define HGEMM_SMEM (NSTAGE * STAGE_B)     // 184320

__global__ __launch_bounds__(512, 1)
void hgemm_nt(const bf16* __restrict__ Ah, const bf16* __restrict__ Al,
              const bf16* __restrict__ Bh, const bf16* __restrict__ Bl,
              const float* __restrict__ bias,
              float* __restrict__ C, bf16* __restrict__ Ch, bf16* __restrict__ Cl,
              int K, int lda, int ldb, int ldc, int Hdim,
              long long sAb, long long sAh_,
              long long sBb, long long sBh_,
              long long sCb, long long sCh_,
              float alpha)
{
    extern __shared__ __align__(128) char smem[];
    const uint32_t sb = smem_u32(smem);

    const int tid  = threadIdx.x;
    const int wid  = tid >> 5;
    const int lane = tid & 31;
    const int wm   = wid >> 2;          // 0..3  (64-row band)
    const int wn   = wid & 3;           // 0..3  (32-col band)

    // batch decomposition
    {
        int z  = blockIdx.z;
        int bz = z / Hdim;
        int hz = z - bz * Hdim;
        long long oA = (long long)bz * sAb + (long long)hz * sAh_
                     + (long long)blockIdx.y * 256 * lda;
        long long oB = (long long)bz * sBb + (long long)hz * sBh_
                     + (long long)blockIdx.x * 128 * ldb;
        long long oC = (long long)bz * sCb + (long long)hz * sCh_
                     + (long long)blockIdx.y * 256 * ldc + (long long)blockIdx.x * 128;
        Ah += oA; Al += oA; Bh += oB; Bl += oB;
        if (C)  C  += oC;
        if (Ch) { Ch += oC; Cl += oC; }
    }

    const int nc = K >> 5;

    // cp.async mapping: A rows 256 (32B per thread), B rows 128 (16B per thread)
    const int rowA = tid >> 1;
    const int cA   = (tid & 1) * 16;     // elems
    const int rowB = tid >> 2;
    const int cB   = (tid & 3) * 8;      // elems
    const bf16* gAh = Ah + (long long)rowA * lda + cA;
    const bf16* gAl = Al + (long long)rowA * lda + cA;
    const bf16* gBh = Bh + (long long)rowB * ldb + cB;
    const bf16* gBl = Bl + (long long)rowB * ldb + cB;
    const uint32_t dA = sb + rowA * ROWB + (tid & 1) * 32;
    const uint32_t dB = sb + OFF_BH + rowB * ROWB + (tid & 3) * 16;

    auto issue = [&](int stage, int c) {
        if (c < nc) {
            const int k0 = c << 5;
            const uint32_t so = stage * STAGE_B;
            cp16(dA + so,          gAh + k0); cp16(dA + so + 16,          gAh + k0 + 8);
            cp16(dA + so + OFF_AL, gAl + k0); cp16(dA + so + OFF_AL + 16, gAl + k0 + 8);
            cp16(dB + so,          gBh + k0);
            cp16(dB + so + B_T_B,  gBl + k0);
        }
        CP_COMMIT();
    };

    float acc[4][4][4];
#pragma unroll
    for (int i = 0; i < 4; i++)
#pragma unroll
        for (int j = 0; j < 4; j++)
#pragma unroll
            for (int r = 0; r < 4; r++) acc[i][j][r] = 0.f;

    issue(0, 0);
    issue(1, 1);

    // ldmatrix lane address component (within a tile): row (lane&15), col half
    const uint32_t loff = (uint32_t)(lane & 15) * ROWB + ((lane >> 4) << 4);

    for (int c = 0; c < nc; c++) {
        CP_WAIT(1);
        __syncthreads();
        issue((c + 2) % NSTAGE, c + 2);

        const uint32_t st    = sb + (c % NSTAGE) * STAGE_B;
        const uint32_t aBase = st + (wm * 64) * ROWB + loff;
        const uint32_t bBase = st + OFF_BH + (wn * 32) * ROWB + loff;

#pragma unroll
        for (int k16 = 0; k16 < 2; k16++) {
            const uint32_t kb = k16 * 32;
            uint32_t bH[2][4], bL[2][4];
#pragma unroll
            for (int nt = 0; nt < 2; nt++) {
                ldm_x4(bH[nt], bBase + nt * (16 * ROWB) + kb);
                ldm_x4(bL[nt], bBase + B_T_B + nt * (16 * ROWB) + kb);
            }
#pragma unroll
            for (int mt = 0; mt < 4; mt++) {
                uint32_t aH[4], aL[4];
                ldm_x4(aH, aBase + mt * (16 * ROWB) + kb);
                ldm_x4(aL, aBase + OFF_AL + mt * (16 * ROWB) + kb);
#pragma unroll
                for (int j = 0; j < 4; j++)
                    mma_bf16(acc[mt][j], aH, bH[j >> 1][j & 1], bH[j >> 1][2 + (j & 1)]);
#pragma unroll
                for (int j = 0; j < 4; j++)
                    mma_bf16(acc[mt][j], aL, bH[j >> 1][j & 1], bH[j >> 1][2 + (j & 1)]);
#pragma unroll
                for (int j = 0; j < 4; j++)
                    mma_bf16(acc[mt][j], aH, bL[j >> 1][j & 1], bL[j >> 1][2 + (j & 1)]);
            }
        }
    }

    // ---- epilogue ----
    const int colblk = blockIdx.x << 7;
#pragma unroll
    for (int mt = 0; mt < 4; mt++) {
        const int row0 = wm * 64 + mt * 16 + (lane >> 2);
#pragma unroll
        for (int hrow = 0; hrow < 2; hrow++) {
            const int row = row0 + hrow * 8;
#pragma unroll
            for (int j = 0; j < 4; j++) {
                const int col = wn * 32 + j * 8 + (lane & 3) * 2;
                float b0 = 0.f, b1 = 0.f;
                if (bias) { b0 = bias[colblk + col]; b1 = bias[colblk + col + 1]; }
                float v0 = acc[mt][j][hrow * 2 + 0] * alpha + b0;
                float v1 = acc[mt][j][hrow * 2 + 1] * alpha + b1;
                const long long ci = (long long)row * ldc + col;
                if (C) *(float2*)(C + ci) = make_float2(v0, v1);
                if (Ch) {
                    bf16 h0, l0, h1, l1;
                    split1(v0, h0, l0);
                    split1(v1, h1, l1);
                    *(bf162*)(Ch + ci) = __halves2bfloat162(h0, h1);
                    *(bf162*)(Cl + ci) = __halves2bfloat162(l0, l1);
                }
            }
        }
    }
}

// ---------------------------------------------------------------------------
// Elementwise fp32 -> (hi,lo) bf16 split
// ---------------------------------------------------------------------------
__global__ void split_arr(const float* __restrict__ s, bf16* __restrict__ h,
                          bf16* __restrict__ l, long long n)
{
    long long i = ((long long)blockIdx.x * blockDim.x + threadIdx.x) * 4;
    if (i >= n) return;
    float4 v = *(const float4*)(s + i);
    bf16 h0, l0, h1, l1, h2, l2, h3, l3;
    split1(v.x, h0, l0); split1(v.y, h1, l1);
    split1(v.z, h2, l2); split1(v.w, h3, l3);
    *(bf162*)(h + i)     = __halves2bfloat162(h0, h1);
    *(bf162*)(h + i + 2) = __halves2bfloat162(h2, h3);
    *(bf162*)(l + i)     = __halves2bfloat162(l0, l1);
    *(bf162*)(l + i + 2) = __halves2bfloat162(l2, l3);
}

// ---------------------------------------------------------------------------
// RoPE + split from packed qkv: reads fp32 (B*S, NQKV) at column offset,
// writes rotated hi/lo bf16 in (bs, Hx, 256) packed layout.
// ---------------------------------------------------------------------------
__global__ void rope_split(const float* __restrict__ x, const int* __restrict__ pos,
                           bf16* __restrict__ xh, bf16* __restrict__ xl,
                           int Hx, int total)
{
    int idx = blockIdx.x * blockDim.x + threadIdx.x;
    if (idx >= total) return;
    int j    = idx & 127;
    int rest = idx >> 7;
    int hh   = rest % Hx;
    int bs   = rest / Hx;
    float p  = (float)pos[bs];
    float inv = __expf(-(float)j * (9.210340371976184f / 128.f));
    float f = p * inv;
    float sn, cs;
    sincosf(f, &sn, &cs);
    long long ioff = (long long)bs * NQKV + hh * DD;    // x column base
    float x1 = x[ioff + j];
    float x2 = x[ioff + 128 + j];
    float y1 = cs * x1 - sn * x2;
    float y2 = sn * x1 + cs * x2;
    long long ooff = ((long long)bs * Hx + hh) * DD;
    bf16 h, l;
    split1(y1, h, l); xh[ooff + j] = h;        xl[ooff + j] = l;
    split1(y2, h, l); xh[ooff + 128 + j] = h;  xl[ooff + 128 + j] = l;
}

// ---------------------------------------------------------------------------
// Transpose v from packed qkv (col 2304) fp32 -> vT (b,D,S) split bf16
// ---------------------------------------------------------------------------
__global__ void transpose_split(const float* __restrict__ qkv,
                                bf16* __restrict__ vTh, bf16* __restrict__ vTl)
{
    __shared__ float t[32][33];
    int b  = blockIdx.z;
    int s0 = blockIdx.x * 32;
    int d0 = blockIdx.y * 32;
    int tx = threadIdx.x, ty = threadIdx.y;
    const float* src = qkv + (long long)b * SS * NQKV + 2304;
#pragma unroll
    for (int i = 0; i < 32; i += 8)
        t[ty + i][tx] = src[(long long)(s0 + ty + i) * NQKV + d0 + tx];
    __syncthreads();
    long long obase = (long long)b * DD * SS;
#pragma unroll
    for (int i = 0; i < 32; i += 8) {
        long long oi = obase + (long long)(d0 + ty + i) * SS + s0 + tx;
        bf16 h, l;
        split1(t[tx][ty + i], h, l);
        vTh[oi] = h;
        vTl[oi] = l;
    }
}

// ---------------------------------------------------------------------------
// Row softmax over attn (B,H,S,S) in place (+mask), also emits split bf16
// ---------------------------------------------------------------------------
__global__ __launch_bounds__(256)
void softmax_split(float* __restrict__ attn, const float* __restrict__ mask,
                   bf16* __restrict__ ah, bf16* __restrict__ al)
{
    const int HSrows = HH * SS;
    long long r = blockIdx.x;
    int b = (int)(r / HSrows);
    float* row = attn + r * (long long)SS;
    const float* mrow = mask + (long long)b * SS;

    int tid  = threadIdx.x;
    int w    = tid >> 5;
    int lane = tid & 31;
    __shared__ float red[8];

    float v[8];
    float mx = -1e30f;
#pragma unroll
    for (int i = 0; i < 8; i++) {
        int c = tid + i * 256;
        float x = row[c] + mrow[c];
        v[i] = x;
        mx = fmaxf(mx, x);
    }
#pragma unroll
    for (int o = 16; o; o >>= 1) mx = fmaxf(mx, __shfl_xor_sync(0xffffffffu, mx, o));
    if (lane == 0) red[w] = mx;
    __syncthreads();
#pragma unroll
    for (int i = 0; i < 8; i++) mx = fmaxf(mx, red[i]);

    float s = 0.f;
#pragma unroll
    for (int i = 0; i < 8; i++) {
        v[i] = __expf(v[i] - mx);
        s += v[i];
    }
#pragma unroll
    for (int o = 16; o; o >>= 1) s += __shfl_xor_sync(0xffffffffu, s, o);
    __syncthreads();
    if (lane == 0) red[w] = s;
    __syncthreads();
    s = 0.f;
#pragma unroll
    for (int i = 0; i < 8; i++) s += red[i];
    float inv = 1.f / s;

    long long rb = r * (long long)SS;
#pragma unroll
    for (int i = 0; i < 8; i++) {
        int c = tid + i * 256;
        float p = v[i] * inv;
        row[c] = p;
        bf16 h, l;
        split1(p, h, l);
        ah[rb + c] = h;
        al[rb + c] = l;
    }
}

// ---------------------------------------------------------------------------
// Launch
// ---------------------------------------------------------------------------
extern "C" void kernel_launch(void* const* d_in, const int* in_sizes, int n_in,
                              void* d_out, int out_size)
{
    (void)in_sizes; (void)n_in; (void)out_size;

    const float* hidden = (const float*)d_in[0];
    const float* mask   = (const float*)d_in[1];
    const int*   pos    = (const int*)  d_in[2];
    const float* Wq     = (const float*)d_in[3];
    const float* bq     = (const float*)d_in[4];
    const float* Wk     = (const float*)d_in[5];
    const float* bk     = (const float*)d_in[6];
    const float* Wv     = (const float*)d_in[7];
    const float* bv     = (const float*)d_in[8];
    const float* Wo     = (const float*)d_in[9];
    const float* bo     = (const float*)d_in[10];

    float* out  = (float*)d_out;                      // (B,S,HID)
    float* attn = out + (size_t)BB * SS * HID_;       // (B,H,S,S)

    float *qkv, *bqkv;
    bf16 *hidH, *hidL, *WqkvH, *WqkvL, *WoH, *WoL;
    bf16 *qH, *qL, *kH, *kL, *vTH, *vTL, *attnH, *attnL, *ctxH, *ctxL;
    cudaGetSymbolAddress((void**)&qkv, g_qkv);
    cudaGetSymbolAddress((void**)&bqkv, g_bqkv);
    cudaGetSymbolAddress((void**)&hidH, g_hidH);   cudaGetSymbolAddress((void**)&hidL, g_hidL);
    cudaGetSymbolAddress((void**)&WqkvH, g_WqkvH); cudaGetSymbolAddress((void**)&WqkvL, g_WqkvL);
    cudaGetSymbolAddress((void**)&WoH, g_WoH);     cudaGetSymbolAddress((void**)&WoL, g_WoL);
    cudaGetSymbolAddress((void**)&qH, g_qH);       cudaGetSymbolAddress((void**)&qL, g_qL);
    cudaGetSymbolAddress((void**)&kH, g_kH);       cudaGetSymbolAddress((void**)&kL, g_kL);
    cudaGetSymbolAddress((void**)&vTH, g_vTH);     cudaGetSymbolAddress((void**)&vTL, g_vTL);
    cudaGetSymbolAddress((void**)&attnH, g_attnH); cudaGetSymbolAddress((void**)&attnL, g_attnL);
    cudaGetSymbolAddress((void**)&ctxH, g_ctxH);   cudaGetSymbolAddress((void**)&ctxL, g_ctxL);

    cudaFuncSetAttribute(hgemm_nt, cudaFuncAttributeMaxDynamicSharedMemorySize,
                         HGEMM_SMEM);

    const int M = BB * SS;   // 4096
    dim3 blk(256);

    // 0) split inputs + pack Wqkv/bias
    {
        long long n;
        n = (long long)BB * SS * HID_;
        split_arr<<<(unsigned)((n / 4 + 255) / 256), blk>>>(hidden, hidH, hidL, n);
        n = (long long)HID_ * HID_;   // Wq rows 0..2047
        split_arr<<<(unsigned)((n / 4 + 255) / 256), blk>>>(Wq, WqkvH, WqkvL, n);
        n = (long long)DD * HID_;     // Wk rows 2048..2303
        split_arr<<<(unsigned)((n / 4 + 255) / 256), blk>>>(
            Wk, WqkvH + (size_t)2048 * HID_, WqkvL + (size_t)2048 * HID_, n);
        // Wv rows 2304..2559
        split_arr<<<(unsigned)((n / 4 + 255) / 256), blk>>>(
            Wv, WqkvH + (size_t)2304 * HID_, WqkvL + (size_t)2304 * HID_, n);
        n = (long long)HID_ * HH * DD;
        split_arr<<<(unsigned)((n / 4 + 255) / 256), blk>>>(Wo, WoH, WoL, n);

        cudaMemcpyAsync(bqkv,        bq, 2048 * sizeof(float), cudaMemcpyDeviceToDevice);
        cudaMemcpyAsync(bqkv + 2048, bk,  256 * sizeof(float), cudaMemcpyDeviceToDevice);
        cudaMemcpyAsync(bqkv + 2304, bv,  256 * sizeof(float), cudaMemcpyDeviceToDevice);
    }

    dim3 gblk(512);

    // 1) fused QKV projection: qkv = hidden @ Wqkv^T + bqkv   (4096 x 2560 x 2048)
    hgemm_nt<<<dim3(NQKV / 128, M / 256, 1), gblk, HGEMM_SMEM>>>(
        hidH, hidL, WqkvH, WqkvL, bqkv, qkv, nullptr, nullptr,
        HID_, HID_, HID_, NQKV, 1, 0, 0, 0, 0, 0, 0, 1.0f);

    // 2) RoPE + split q (cols 0..2047) and k (cols 2048..2303)
    {
        int totq = BB * SS * HH * (DD / 2);
        rope_split<<<(totq + 255) / 256, blk>>>(qkv, pos, qH, qL, HH, totq);
        int totk = BB * SS * (DD / 2);
        rope_split<<<(totk + 255) / 256, blk>>>(qkv + 2048, pos, kH, kL, 1, totk);
    }

    // 3) vT split (b,D,S) from qkv cols 2304..2559
    transpose_split<<<dim3(SS / 32, DD / 32, BB), dim3(32, 8)>>>(qkv, vTH, vTL);

    // 4) scores = (q @ k^T)/16 -> attn fp32 region
    hgemm_nt<<<dim3(SS / 128, SS / 256, BB * HH), gblk, HGEMM_SMEM>>>(
        qH, qL, kH, kL, nullptr, attn, nullptr, nullptr,
        DD, HH * DD, DD, SS, HH,
        (long long)SS * HH * DD, (long long)DD,
        (long long)SS * DD, 0,
        (long long)HH * SS * SS, (long long)SS * SS,
        0.0625f);

    // 5) softmax in place + split output
    softmax_split<<<BB * HH * SS, blk>>>(attn, mask, attnH, attnL);

    // 6) ctx = attn @ v  -> split bf16 directly
    hgemm_nt<<<dim3(DD / 128, SS / 256, BB * HH), gblk, HGEMM_SMEM>>>(
        attnH, attnL, vTH, vTL, nullptr, nullptr, ctxH, ctxL,
        SS, SS, SS, HH * DD, HH,
        (long long)HH * SS * SS, (long long)SS * SS,
        (long long)DD * SS, 0,
        (long long)SS * HH * DD, (long long)DD,
        1.0f);

    // 7) out = ctx @ Wo^T + bo
    hgemm_nt<<<dim3(HID_ / 128, M / 256, 1), gblk, HGEMM_SMEM>>>(
        ctxH, ctxL, WoH, WoL, bo, out, nullptr, nullptr,
        HH * DD, HH * DD, HH * DD, HID_, 1, 0, 0, 0, 0, 0, 0, 1.0f);
}

// round 7
// speedup vs baseline: 2.3861x; 1.0001x over previous
#include <cuda_runtime.h>
#include <cuda_bf16.h>
#include <math.h>
#include <stdint.h>

// Problem constants (Gemma attention, B=2,S=2048,HID=2048,H=8,KH=1,D=256)
#define BB   2
#define SS   2048
#define HID_ 2048
#define HH   8
#define DD   256
#define NQKV 2560   // packed Q(2048) + K(256) + V(256)

typedef __nv_bfloat16 bf16;
typedef __nv_bfloat162 bf162;

// ---------------------------------------------------------------------------
// Scratch (__device__ globals — allocation-free)
// ---------------------------------------------------------------------------
__device__ float g_qkv[(size_t)BB * SS * NQKV];       // 41.9 MB fp32 qkv proj
__device__ float g_bqkv[NQKV];

__device__ bf16 g_hidH[(size_t)BB * SS * HID_], g_hidL[(size_t)BB * SS * HID_];
__device__ bf16 g_WqkvH[(size_t)NQKV * HID_],  g_WqkvL[(size_t)NQKV * HID_];
__device__ bf16 g_WoH[(size_t)HID_ * HH * DD], g_WoL[(size_t)HID_ * HH * DD];
__device__ bf16 g_qH[(size_t)BB * SS * HH * DD], g_qL[(size_t)BB * SS * HH * DD];
__device__ bf16 g_kH[(size_t)BB * SS * DD],      g_kL[(size_t)BB * SS * DD];
__device__ bf16 g_vTH[(size_t)BB * DD * SS],     g_vTL[(size_t)BB * DD * SS];
__device__ bf16 g_attnH[(size_t)BB * HH * SS * SS];   // 134 MB
__device__ bf16 g_attnL[(size_t)BB * HH * SS * SS];   // 134 MB
__device__ bf16 g_ctxH[(size_t)BB * SS * HH * DD],  g_ctxL[(size_t)BB * SS * HH * DD];

// ---------------------------------------------------------------------------
// PTX helpers (sm_80-era: cp.async / ldmatrix / mma.sync — valid on sm_103)
// ---------------------------------------------------------------------------
__device__ __forceinline__ uint32_t smem_u32(const void* p) {
    uint32_t a;
    asm("{ .reg .u64 t; cvta.to.shared.u64 t, %1; cvt.u32.u64 %0, t; }"
        : "=r"(a) : "l"(p));
    return a;
}

__device__ __forceinline__ void cp16(uint32_t dst, const void* src) {
    asm volatile("cp.async.cg.shared.global [%0], [%1], 16;"
                 :: "r"(dst), "l"(src) : "memory");
}
#define CP_COMMIT() asm volatile("cp.async.commit_group;" ::: "memory")
#define CP_WAIT(n)  asm volatile("cp.async.wait_group %0;" :: "n"(n) : "memory")

__device__ __forceinline__ void ldm_x4(uint32_t* r, uint32_t addr) {
    asm volatile("ldmatrix.sync.aligned.m8n8.x4.shared.b16 {%0,%1,%2,%3}, [%4];"
                 : "=r"(r[0]), "=r"(r[1]), "=r"(r[2]), "=r"(r[3]) : "r"(addr));
}

__device__ __forceinline__ void mma_bf16(float* c, const uint32_t* a,
                                         uint32_t b0, uint32_t b1) {
    asm volatile(
        "mma.sync.aligned.m16n8k16.row.col.f32.bf16.bf16.f32 "
        "{%0,%1,%2,%3}, {%4,%5,%6,%7}, {%8,%9}, {%0,%1,%2,%3};"
        : "+f"(c[0]), "+f"(c[1]), "+f"(c[2]), "+f"(c[3])
        : "r"(a[0]), "r"(a[1]), "r"(a[2]), "r"(a[3]), "r"(b0), "r"(b1));
}

__device__ __forceinline__ void split1(float v, bf16& h, bf16& l) {
    h = __float2bfloat16(v);
    l = __float2bfloat16(v - __bfloat162float(h));
}

// ===========================================================================
// Split-bf16 NT GEMM on HMMA:  C = alpha*(Ah·Bh^T + Al·Bh^T + Ah·Bl^T) + bias
//   Tile 256x128x32, 512 threads (16 warps, warp tile 64x32), 3-stage
//   cp.async pipeline. All dims multiples of (256,128,32).
// ===========================================================================
#define ROWB    80                  // 32 bf16 (64B) + 16B pad
#define A_T_B   (256 * ROWB)        // 20480
#define B_T_B   (128 * ROWB)        // 10240
#define OFF_AL  A_T_B               // 20480
#define OFF_BH  (2 * A_T_B)         // 40960
#define OFF_BL  (2 * A_T_B + B_T_B) // 51200
#define STAGE_B (2 * A_T_B + 2 * B_T_B)   // 61440
#define NSTAGE  3
#define HGEMM_SMEM (NSTAGE * STAGE_B)     // 184320

__global__ __launch_bounds__(512, 1)
void hgemm_nt(const bf16* __restrict__ Ah, const bf16* __restrict__ Al,
              const bf16* __restrict__ Bh, const bf16* __restrict__ Bl,
              const float* __restrict__ bias,
              float* __restrict__ C, bf16* __restrict__ Ch, bf16* __restrict__ Cl,
              int K, int lda, int ldb, int ldc, int Hdim,
              long long sAb, long long sAh_,
              long long sBb, long long sBh_,
              long long sCb, long long sCh_,
              float alpha)
{
    extern __shared__ __align__(128) char smem[];
    const uint32_t sb = smem_u32(smem);

    const int tid  = threadIdx.x;
    const int wid  = tid >> 5;
    const int lane = tid & 31;
    const int wm   = wid >> 2;          // 0..3  (64-row band)
    const int wn   = wid & 3;           // 0..3  (32-col band)

    // batch decomposition
    {
        int z  = blockIdx.z;
        int bz = z / Hdim;
        int hz = z - bz * Hdim;
        long long oA = (long long)bz * sAb + (long long)hz * sAh_
                     + (long long)blockIdx.y * 256 * lda;
        long long oB = (long long)bz * sBb + (long long)hz * sBh_
                     + (long long)blockIdx.x * 128 * ldb;
        long long oC = (long long)bz * sCb + (long long)hz * sCh_
                     + (long long)blockIdx.y * 256 * ldc + (long long)blockIdx.x * 128;
        Ah += oA; Al += oA; Bh += oB; Bl += oB;
        if (C)  C  += oC;
        if (Ch) { Ch += oC; Cl += oC; }
    }

    const int nc = K >> 5;

    // cp.async mapping: A rows 256 (32B per thread), B rows 128 (16B per thread)
    const int rowA = tid >> 1;
    const int cA   = (tid & 1) * 16;     // elems
    const int rowB = tid >> 2;
    const int cB   = (tid & 3) * 8;      // elems
    const bf16* gAh = Ah + (long long)rowA * lda + cA;
    const bf16* gAl = Al + (long long)rowA * lda + cA;
    const bf16* gBh = Bh + (long long)rowB * ldb + cB;
    const bf16* gBl = Bl + (long long)rowB * ldb + cB;
    const uint32_t dA = sb + rowA * ROWB + (tid & 1) * 32;
    const uint32_t dB = sb + OFF_BH + rowB * ROWB + (tid & 3) * 16;

    auto issue = [&](int stage, int c) {
        if (c < nc) {
            const int k0 = c << 5;
            const uint32_t so = stage * STAGE_B;
            cp16(dA + so,          gAh + k0); cp16(dA + so + 16,          gAh + k0 + 8);
            cp16(dA + so + OFF_AL, gAl + k0); cp16(dA + so + OFF_AL + 16, gAl + k0 + 8);
            cp16(dB + so,          gBh + k0);
            cp16(dB + so + B_T_B,  gBl + k0);
        }
        CP_COMMIT();
    };

    float acc[4][4][4];
#pragma unroll
    for (int i = 0; i < 4; i++)
#pragma unroll
        for (int j = 0; j < 4; j++)
#pragma unroll
            for (int r = 0; r < 4; r++) acc[i][j][r] = 0.f;

    issue(0, 0);
    issue(1, 1);

    // ldmatrix lane address component (within a tile): row (lane&15), col half
    const uint32_t loff = (uint32_t)(lane & 15) * ROWB + ((lane >> 4) << 4);

    for (int c = 0; c < nc; c++) {
        CP_WAIT(1);
        __syncthreads();
        issue((c + 2) % NSTAGE, c + 2);

        const uint32_t st    = sb + (c % NSTAGE) * STAGE_B;
        const uint32_t aBase = st + (wm * 64) * ROWB + loff;
        const uint32_t bBase = st + OFF_BH + (wn * 32) * ROWB + loff;

#pragma unroll
        for (int k16 = 0; k16 < 2; k16++) {
            const uint32_t kb = k16 * 32;
            uint32_t bH[2][4], bL[2][4];
#pragma unroll
            for (int nt = 0; nt < 2; nt++) {
                ldm_x4(bH[nt], bBase + nt * (16 * ROWB) + kb);
                ldm_x4(bL[nt], bBase + B_T_B + nt * (16 * ROWB) + kb);
            }
#pragma unroll
            for (int mt = 0; mt < 4; mt++) {
                uint32_t aH[4], aL[4];
                ldm_x4(aH, aBase + mt * (16 * ROWB) + kb);
                ldm_x4(aL, aBase + OFF_AL + mt * (16 * ROWB) + kb);
#pragma unroll
                for (int j = 0; j < 4; j++)
                    mma_bf16(acc[mt][j], aH, bH[j >> 1][j & 1], bH[j >> 1][2 + (j & 1)]);
#pragma unroll
                for (int j = 0; j < 4; j++)
                    mma_bf16(acc[mt][j], aL, bH[j >> 1][j & 1], bH[j >> 1][2 + (j & 1)]);
#pragma unroll
                for (int j = 0; j < 4; j++)
                    mma_bf16(acc[mt][j], aH, bL[j >> 1][j & 1], bL[j >> 1][2 + (j & 1)]);
            }
        }
    }

    // ---- epilogue ----
    const int colblk = blockIdx.x << 7;
#pragma unroll
    for (int mt = 0; mt < 4; mt++) {
        const int row0 = wm * 64 + mt * 16 + (lane >> 2);
#pragma unroll
        for (int hrow = 0; hrow < 2; hrow++) {
            const int row = row0 + hrow * 8;
#pragma unroll
            for (int j = 0; j < 4; j++) {
                const int col = wn * 32 + j * 8 + (lane & 3) * 2;
                float b0 = 0.f, b1 = 0.f;
                if (bias) { b0 = bias[colblk + col]; b1 = bias[colblk + col + 1]; }
                float v0 = acc[mt][j][hrow * 2 + 0] * alpha + b0;
                float v1 = acc[mt][j][hrow * 2 + 1] * alpha + b1;
                const long long ci = (long long)row * ldc + col;
                if (C) *(float2*)(C + ci) = make_float2(v0, v1);
                if (Ch) {
                    bf16 h0, l0, h1, l1;
                    split1(v0, h0, l0);
                    split1(v1, h1, l1);
                    *(bf162*)(Ch + ci) = __halves2bfloat162(h0, h1);
                    *(bf162*)(Cl + ci) = __halves2bfloat162(l0, l1);
                }
            }
        }
    }
}

// ---------------------------------------------------------------------------
// Elementwise fp32 -> (hi,lo) bf16 split
// ---------------------------------------------------------------------------
__global__ void split_arr(const float* __restrict__ s, bf16* __restrict__ h,
                          bf16* __restrict__ l, long long n)
{
    long long i = ((long long)blockIdx.x * blockDim.x + threadIdx.x) * 4;
    if (i >= n) return;
    float4 v = *(const float4*)(s + i);
    bf16 h0, l0, h1, l1, h2, l2, h3, l3;
    split1(v.x, h0, l0); split1(v.y, h1, l1);
    split1(v.z, h2, l2); split1(v.w, h3, l3);
    *(bf162*)(h + i)     = __halves2bfloat162(h0, h1);
    *(bf162*)(h + i + 2) = __halves2bfloat162(h2, h3);
    *(bf162*)(l + i)     = __halves2bfloat162(l0, l1);
    *(bf162*)(l + i + 2) = __halves2bfloat162(l2, l3);
}

// ---------------------------------------------------------------------------
// RoPE + split from packed qkv: reads fp32 (B*S, NQKV) at column offset,
// writes rotated hi/lo bf16 in (bs, Hx, 256) packed layout.
// ---------------------------------------------------------------------------
__global__ void rope_split(const float* __restrict__ x, const int* __restrict__ pos,
                           bf16* __restrict__ xh, bf16* __restrict__ xl,
                           int Hx, int total)
{
    int idx = blockIdx.x * blockDim.x + threadIdx.x;
    if (idx >= total) return;
    int j    = idx & 127;
    int rest = idx >> 7;
    int hh   = rest % Hx;
    int bs   = rest / Hx;
    float p  = (float)pos[bs];
    float inv = __expf(-(float)j * (9.210340371976184f / 128.f));
    float f = p * inv;
    float sn, cs;
    sincosf(f, &sn, &cs);
    long long ioff = (long long)bs * NQKV + hh * DD;    // x column base
    float x1 = x[ioff + j];
    float x2 = x[ioff + 128 + j];
    float y1 = cs * x1 - sn * x2;
    float y2 = sn * x1 + cs * x2;
    long long ooff = ((long long)bs * Hx + hh) * DD;
    bf16 h, l;
    split1(y1, h, l); xh[ooff + j] = h;        xl[ooff + j] = l;
    split1(y2, h, l); xh[ooff + 128 + j] = h;  xl[ooff + 128 + j] = l;
}

// ---------------------------------------------------------------------------
// Transpose v from packed qkv (col 2304) fp32 -> vT (b,D,S) split bf16
// ---------------------------------------------------------------------------
__global__ void transpose_split(const float* __restrict__ qkv,
                                bf16* __restrict__ vTh, bf16* __restrict__ vTl)
{
    __shared__ float t[32][33];
    int b  = blockIdx.z;
    int s0 = blockIdx.x * 32;
    int d0 = blockIdx.y * 32;
    int tx = threadIdx.x, ty = threadIdx.y;
    const float* src = qkv + (long long)b * SS * NQKV + 2304;
#pragma unroll
    for (int i = 0; i < 32; i += 8)
        t[ty + i][tx] = src[(long long)(s0 + ty + i) * NQKV + d0 + tx];
    __syncthreads();
    long long obase = (long long)b * DD * SS;
#pragma unroll
    for (int i = 0; i < 32; i += 8) {
        long long oi = obase + (long long)(d0 + ty + i) * SS + s0 + tx;
        bf16 h, l;
        split1(t[tx][ty + i], h, l);
        vTh[oi] = h;
        vTl[oi] = l;
    }
}

// ---------------------------------------------------------------------------
// Row softmax over attn (B,H,S,S) in place (+mask), also emits split bf16
// ---------------------------------------------------------------------------
__global__ __launch_bounds__(256)
void softmax_split(float* __restrict__ attn, const float* __restrict__ mask,
                   bf16* __restrict__ ah, bf16* __restrict__ al)
{
    const int HSrows = HH * SS;
    long long r = blockIdx.x;
    int b = (int)(r / HSrows);
    float* row = attn + r * (long long)SS;
    const float* mrow = mask + (long long)b * SS;

    int tid  = threadIdx.x;
    int w    = tid >> 5;
    int lane = tid & 31;
    __shared__ float red[8];

    float v[8];
    float mx = -1e30f;
#pragma unroll
    for (int i = 0; i < 8; i++) {
        int c = tid + i * 256;
        float x = row[c] + mrow[c];
        v[i] = x;
        mx = fmaxf(mx, x);
    }
#pragma unroll
    for (int o = 16; o; o >>= 1) mx = fmaxf(mx, __shfl_xor_sync(0xffffffffu, mx, o));
    if (lane == 0) red[w] = mx;
    __syncthreads();
#pragma unroll
    for (int i = 0; i < 8; i++) mx = fmaxf(mx, red[i]);

    float s = 0.f;
#pragma unroll
    for (int i = 0; i < 8; i++) {
        v[i] = __expf(v[i] - mx);
        s += v[i];
    }
#pragma unroll
    for (int o = 16; o; o >>= 1) s += __shfl_xor_sync(0xffffffffu, s, o);
    __syncthreads();
    if (lane == 0) red[w] = s;
    __syncthreads();
    s = 0.f;
#pragma unroll
    for (int i = 0; i < 8; i++) s += red[i];
    float inv = 1.f / s;

    long long rb = r * (long long)SS;
#pragma unroll
    for (int i = 0; i < 8; i++) {
        int c = tid + i * 256;
        float p = v[i] * inv;
        row[c] = p;
        bf16 h, l;
        split1(p, h, l);
        ah[rb + c] = h;
        al[rb + c] = l;
    }
}

// ---------------------------------------------------------------------------
// Launch
// ---------------------------------------------------------------------------
extern "C" void kernel_launch(void* const* d_in, const int* in_sizes, int n_in,
                              void* d_out, int out_size)
{
    (void)in_sizes; (void)n_in; (void)out_size;

    const float* hidden = (const float*)d_in[0];
    const float* mask   = (const float*)d_in[1];
    const int*   pos    = (const int*)  d_in[2];
    const float* Wq     = (const float*)d_in[3];
    const float* bq     = (const float*)d_in[4];
    const float* Wk     = (const float*)d_in[5];
    const float* bk     = (const float*)d_in[6];
    const float* Wv     = (const float*)d_in[7];
    const float* bv     = (const float*)d_in[8];
    const float* Wo     = (const float*)d_in[9];
    const float* bo     = (const float*)d_in[10];

    float* out  = (float*)d_out;                      // (B,S,HID)
    float* attn = out + (size_t)BB * SS * HID_;       // (B,H,S,S)

    float *qkv, *bqkv;
    bf16 *hidH, *hidL, *WqkvH, *WqkvL, *WoH, *WoL;
    bf16 *qH, *qL, *kH, *kL, *vTH, *vTL, *attnH, *attnL, *ctxH, *ctxL;
    cudaGetSymbolAddress((void**)&qkv, g_qkv);
    cudaGetSymbolAddress((void**)&bqkv, g_bqkv);
    cudaGetSymbolAddress((void**)&hidH, g_hidH);   cudaGetSymbolAddress((void**)&hidL, g_hidL);
    cudaGetSymbolAddress((void**)&WqkvH, g_WqkvH); cudaGetSymbolAddress((void**)&WqkvL, g_WqkvL);
    cudaGetSymbolAddress((void**)&WoH, g_WoH);     cudaGetSymbolAddress((void**)&WoL, g_WoL);
    cudaGetSymbolAddress((void**)&qH, g_qH);       cudaGetSymbolAddress((void**)&qL, g_qL);
    cudaGetSymbolAddress((void**)&kH, g_kH);       cudaGetSymbolAddress((void**)&kL, g_kL);
    cudaGetSymbolAddress((void**)&vTH, g_vTH);     cudaGetSymbolAddress((void**)&vTL, g_vTL);
    cudaGetSymbolAddress((void**)&attnH, g_attnH); cudaGetSymbolAddress((void**)&attnL, g_attnL);
    cudaGetSymbolAddress((void**)&ctxH, g_ctxH);   cudaGetSymbolAddress((void**)&ctxL, g_ctxL);

    cudaFuncSetAttribute(hgemm_nt, cudaFuncAttributeMaxDynamicSharedMemorySize,
                         HGEMM_SMEM);

    const int M = BB * SS;   // 4096
    dim3 blk(256);

    // 0) split inputs + pack Wqkv/bias
    {
        long long n;
        n = (long long)BB * SS * HID_;
        split_arr<<<(unsigned)((n / 4 + 255) / 256), blk>>>(hidden, hidH, hidL, n);
        n = (long long)HID_ * HID_;   // Wq rows 0..2047
        split_arr<<<(unsigned)((n / 4 + 255) / 256), blk>>>(Wq, WqkvH, WqkvL, n);
        n = (long long)DD * HID_;     // Wk rows 2048..2303
        split_arr<<<(unsigned)((n / 4 + 255) / 256), blk>>>(
            Wk, WqkvH + (size_t)2048 * HID_, WqkvL + (size_t)2048 * HID_, n);
        // Wv rows 2304..2559
        split_arr<<<(unsigned)((n / 4 + 255) / 256), blk>>>(
            Wv, WqkvH + (size_t)2304 * HID_, WqkvL + (size_t)2304 * HID_, n);
        n = (long long)HID_ * HH * DD;
        split_arr<<<(unsigned)((n / 4 + 255) / 256), blk>>>(Wo, WoH, WoL, n);

        cudaMemcpyAsync(bqkv,        bq, 2048 * sizeof(float), cudaMemcpyDeviceToDevice);
        cudaMemcpyAsync(bqkv + 2048, bk,  256 * sizeof(float), cudaMemcpyDeviceToDevice);
        cudaMemcpyAsync(bqkv + 2304, bv,  256 * sizeof(float), cudaMemcpyDeviceToDevice);
    }

    dim3 gblk(512);

    // 1) fused QKV projection: qkv = hidden @ Wqkv^T + bqkv   (4096 x 2560 x 2048)
    hgemm_nt<<<dim3(NQKV / 128, M / 256, 1), gblk, HGEMM_SMEM>>>(
        hidH, hidL, WqkvH, WqkvL, bqkv, qkv, nullptr, nullptr,
        HID_, HID_, HID_, NQKV, 1, 0, 0, 0, 0, 0, 0, 1.0f);

    // 2) RoPE + split q (cols 0..2047) and k (cols 2048..2303)
    {
        int totq = BB * SS * HH * (DD / 2);
        rope_split<<<(totq + 255) / 256, blk>>>(qkv, pos, qH, qL, HH, totq);
        int totk = BB * SS * (DD / 2);
        rope_split<<<(totk + 255) / 256, blk>>>(qkv + 2048, pos, kH, kL, 1, totk);
    }

    // 3) vT split (b,D,S) from qkv cols 2304..2559
    transpose_split<<<dim3(SS / 32, DD / 32, BB), dim3(32, 8)>>>(qkv, vTH, vTL);

    // 4) scores = (q @ k^T)/16 -> attn fp32 region
    hgemm_nt<<<dim3(SS / 128, SS / 256, BB * HH), gblk, HGEMM_SMEM>>>(
        qH, qL, kH, kL, nullptr, attn, nullptr, nullptr,
        DD, HH * DD, DD, SS, HH,
        (long long)SS * HH * DD, (long long)DD,
        (long long)SS * DD, 0,
        (long long)HH * SS * SS, (long long)SS * SS,
        0.0625f);

    // 5) softmax in place + split output
    softmax_split<<<BB * HH * SS, blk>>>(attn, mask, attnH, attnL);

    // 6) ctx = attn @ v  -> split bf16 directly
    hgemm_nt<<<dim3(DD / 128, SS / 256, BB * HH), gblk, HGEMM_SMEM>>>(
        attnH, attnL, vTH, vTL, nullptr, nullptr, ctxH, ctxL,
        SS, SS, SS, HH * DD, HH,
        (long long)HH * SS * SS, (long long)SS * SS,
        (long long)DD * SS, 0,
        (long long)SS * HH * DD, (long long)DD,
        1.0f);

    // 7) out = ctx @ Wo^T + bo
    hgemm_nt<<<dim3(HID_ / 128, M / 256, 1), gblk, HGEMM_SMEM>>>(
        ctxH, ctxL, WoH, WoL, bo, out, nullptr, nullptr,
        HH * DD, HH * DD, HH * DD, HID_, 1, 0, 0, 0, 0, 0, 0, 1.0f);
}